// round 2
// baseline (speedup 1.0000x reference)
#include <cuda_runtime.h>

// Problem constants
#define B_SZ 2
#define T_SZ 2048
#define C_SZ 1024
#define NH   16
#define HD   64
#define M_ROWS (B_SZ * T_SZ)     // 4096
#define N_QKV  (3 * C_SZ)        // 3072

typedef unsigned long long u64;

// Scratch (no allocations allowed -> __device__ globals)
__device__ float g_q[(size_t)B_SZ * NH * T_SZ * HD];   // [B,H,T,hd]
__device__ float g_k[(size_t)B_SZ * NH * T_SZ * HD];
__device__ float g_v[(size_t)B_SZ * NH * T_SZ * HD];
__device__ float g_att[(size_t)M_ROWS * C_SZ];         // [B,T,C]

// ---------------------------------------------------------------------------
// Packed f32x2 helpers (Blackwell): 2 fp32 FLOPs per lane per instruction.
// ptxas will not auto-fuse these from C++.
// ---------------------------------------------------------------------------
__device__ __forceinline__ u64 dup2(float a) {
    u64 r; asm("mov.b64 %0, {%1, %1};" : "=l"(r) : "f"(a)); return r;
}
__device__ __forceinline__ void ffma2(u64 &c, u64 a, u64 b) {
    asm("fma.rn.f32x2 %0, %1, %2, %0;" : "+l"(c) : "l"(a), "l"(b));
}
__device__ __forceinline__ u64 fmul2(u64 a, u64 b) {
    u64 r; asm("mul.rn.f32x2 %0, %1, %2;" : "=l"(r) : "l"(a), "l"(b)); return r;
}
__device__ __forceinline__ u64 fadd2(u64 a, u64 b) {
    u64 r; asm("add.rn.f32x2 %0, %1, %2;" : "=l"(r) : "l"(a), "l"(b)); return r;
}
__device__ __forceinline__ float2 unpk(u64 v) {
    float2 r; asm("mov.b64 {%0, %1}, %2;" : "=f"(r.x), "=f"(r.y) : "l"(v)); return r;
}

// ---------------------------------------------------------------------------
// SGEMM: C = A @ B + bias, 128x128 tile, BK=8, 8x8/thread, 256 thr,
// double-buffered smem, A stored DUPLICATED (a,a) so FFMA2 multiplicand
// pairs come straight from LDS.128 with zero pack instructions.
// MODE 0: A = x, epilogue scatters qkv into g_q/g_k/g_v ([B,H,T,hd])
// MODE 1: A = g_att, epilogue writes Cout row-major
// ---------------------------------------------------------------------------
#define BM 128
#define BN 128
#define BK 8

template <int MODE>
__global__ __launch_bounds__(256, 2)
void sgemm_bias(const float* __restrict__ A,
                const float* __restrict__ Bmat,
                const float* __restrict__ bias,
                float* __restrict__ Cout,
                int M, int N, int K)
{
    __shared__ float As2[2][BK][2 * BM];   // duplicated pairs
    __shared__ float Bs[2][BK][BN];

    const int tid = threadIdx.x;
    const int bx = blockIdx.x, by = blockIdx.y;

    const float* Ap = (MODE == 1) ? g_att : A;

    // A tile loader: 128 rows x 8 cols, one float4 per thread
    const int rowA = tid >> 1;
    const int colA = (tid & 1) * 4;
    // B tile loader: 8 rows x 128 cols, one float4 per thread
    const int rowB = tid >> 5;
    const int colB = (tid & 31) * 4;

    const float* Abase = Ap + (size_t)(by * BM + rowA) * K + colA;
    const float* Bbase = Bmat + (size_t)rowB * N + bx * BN + colB;

    const int tx = tid & 15;
    const int ty = tid >> 4;

    u64 acc[8][4];
    #pragma unroll
    for (int i = 0; i < 8; i++)
        #pragma unroll
        for (int j = 0; j < 4; j++)
            acc[i][j] = 0ull;   // (0.0f, 0.0f)

    const int nk = K / BK;

    // preload tile 0
    float4 a4 = *reinterpret_cast<const float4*>(Abase);
    float4 b4 = *reinterpret_cast<const float4*>(Bbase);
    {
        *reinterpret_cast<float2*>(&As2[0][colA + 0][2 * rowA]) = make_float2(a4.x, a4.x);
        *reinterpret_cast<float2*>(&As2[0][colA + 1][2 * rowA]) = make_float2(a4.y, a4.y);
        *reinterpret_cast<float2*>(&As2[0][colA + 2][2 * rowA]) = make_float2(a4.z, a4.z);
        *reinterpret_cast<float2*>(&As2[0][colA + 3][2 * rowA]) = make_float2(a4.w, a4.w);
        *reinterpret_cast<float4*>(&Bs[0][rowB][colB]) = b4;
    }
    __syncthreads();

    for (int kt = 0; kt < nk; kt++) {
        const int cur = kt & 1;
        // prefetch next tile into registers (latency hidden by compute)
        if (kt + 1 < nk) {
            a4 = *reinterpret_cast<const float4*>(Abase + (kt + 1) * BK);
            b4 = *reinterpret_cast<const float4*>(Bbase + (size_t)(kt + 1) * BK * N);
        }

        #pragma unroll
        for (int kk = 0; kk < BK; kk++) {
            const ulonglong2* ap = reinterpret_cast<const ulonglong2*>(&As2[cur][kk][ty * 16]);
            const ulonglong2* bp = reinterpret_cast<const ulonglong2*>(&Bs[cur][kk][tx * 8]);
            ulonglong2 ra01 = ap[0], ra23 = ap[1], ra45 = ap[2], ra67 = ap[3];
            ulonglong2 rb01 = bp[0], rb23 = bp[1];
            u64 ra[8] = {ra01.x, ra01.y, ra23.x, ra23.y, ra45.x, ra45.y, ra67.x, ra67.y};
            u64 rb[4] = {rb01.x, rb01.y, rb23.x, rb23.y};
            #pragma unroll
            for (int i = 0; i < 8; i++)
                #pragma unroll
                for (int j = 0; j < 4; j++)
                    ffma2(acc[i][j], ra[i], rb[j]);
        }

        if (kt + 1 < nk) {
            const int nxt = cur ^ 1;
            *reinterpret_cast<float2*>(&As2[nxt][colA + 0][2 * rowA]) = make_float2(a4.x, a4.x);
            *reinterpret_cast<float2*>(&As2[nxt][colA + 1][2 * rowA]) = make_float2(a4.y, a4.y);
            *reinterpret_cast<float2*>(&As2[nxt][colA + 2][2 * rowA]) = make_float2(a4.z, a4.z);
            *reinterpret_cast<float2*>(&As2[nxt][colA + 3][2 * rowA]) = make_float2(a4.w, a4.w);
            *reinterpret_cast<float4*>(&Bs[nxt][rowB][colB]) = b4;
            __syncthreads();
        }
    }

    const int mbase = by * BM + ty * 8;
    const int nbase = bx * BN + tx * 8;

    if (MODE == 0) {
        // n -> head h = n/192, inner = n%192 ; inner<64 -> q, <128 -> k, else v
        #pragma unroll
        for (int jp = 0; jp < 4; jp++) {
            #pragma unroll
            for (int jl = 0; jl < 2; jl++) {
                const int n = nbase + jp * 2 + jl;
                const int h = n / 192;
                const int inner = n - h * 192;
                const int which = inner >> 6;
                const int d = inner & 63;
                const float bv = bias[n];
                float* dst = (which == 0) ? g_q : (which == 1) ? g_k : g_v;
                #pragma unroll
                for (int i = 0; i < 8; i++) {
                    const int mm = mbase + i;
                    const int b = mm >> 11;           // /2048
                    const int t = mm & (T_SZ - 1);
                    float2 v2 = unpk(acc[i][jp]);
                    dst[(((size_t)(b * NH + h) * T_SZ + t) * HD) + d] =
                        ((jl == 0) ? v2.x : v2.y) + bv;
                }
            }
        }
    } else {
        const ulonglong2* bb = reinterpret_cast<const ulonglong2*>(&bias[nbase]);
        ulonglong2 bb0 = bb[0], bb1 = bb[1];
        #pragma unroll
        for (int i = 0; i < 8; i++) {
            const int mm = mbase + i;
            ulonglong2 s0, s1;
            s0.x = fadd2(acc[i][0], bb0.x);
            s0.y = fadd2(acc[i][1], bb0.y);
            s1.x = fadd2(acc[i][2], bb1.x);
            s1.y = fadd2(acc[i][3], bb1.y);
            ulonglong2* op = reinterpret_cast<ulonglong2*>(&Cout[(size_t)mm * N + nbase]);
            op[0] = s0;
            op[1] = s1;
        }
    }
}

// ---------------------------------------------------------------------------
// Causal flash attention. grid = (T/64, B*NH), 256 threads.
// Br=Bc=64, hd=64. Dynamic smem: Qt[64][64] + Kt[64][64] + Vs[64][64] + Ss[64][65]
// Phase A: S = Q K^T / 8, FFMA2 (4x4 per thread as 4x2 pairs), causal-masked.
// Phase B: per-row online softmax (4 lanes/row), O accumulated as 8 f32x2 regs.
// ---------------------------------------------------------------------------
#define FA_SMEM_FLOATS (3 * 64 * 64 + 64 * 65)
#define FA_SMEM_BYTES  (FA_SMEM_FLOATS * 4)

__global__ __launch_bounds__(256, 3)
void flash_attn()
{
    extern __shared__ float sm[];
    float* Qt = sm;                 // [d][i]  d-major
    float* Kt = sm + 64 * 64;       // [d][j]
    float* Vs = sm + 2 * 64 * 64;   // [j][d]
    float* Ss = sm + 3 * 64 * 64;   // [i][j], leading dim 65

    const int tid = threadIdx.x;
    const int bh = blockIdx.y;                  // b*NH + h
    const int qbase = blockIdx.x * 64;
    const size_t base = (size_t)bh * T_SZ * HD;
    const float* qp = g_q + base;
    const float* kp = g_k + base;
    const float* vp = g_v + base;

    const int li = tid >> 2;        // row 0..63 (loader row & phase-B row)
    const int c0 = (tid & 3) * 16;  // 16-wide chunk (cols of S / dims of V,O)

    // Load Q tile transposed
    #pragma unroll
    for (int u = 0; u < 16; u += 4) {
        float4 v4 = *reinterpret_cast<const float4*>(qp + (size_t)(qbase + li) * HD + c0 + u);
        Qt[(c0 + u + 0) * 64 + li] = v4.x;
        Qt[(c0 + u + 1) * 64 + li] = v4.y;
        Qt[(c0 + u + 2) * 64 + li] = v4.z;
        Qt[(c0 + u + 3) * 64 + li] = v4.w;
    }

    const int tx = tid & 15;        // phase-A col group (4 cols)
    const int ty = tid >> 4;        // phase-A row group (4 rows)
    const int qg0 = qbase + ty * 4;

    float m = -1e30f, l = 0.0f;
    u64 o2[8];
    #pragma unroll
    for (int i = 0; i < 8; i++) o2[i] = 0ull;
    const float inv_scale = 0.125f;  // 1/sqrt(64)

    const int ntiles = blockIdx.x + 1;   // causal: tiles 0..qtile
    for (int kt = 0; kt < ntiles; kt++) {
        const int kbase = kt * 64;
        __syncthreads();   // prior phase-B reads of Vs/Ss complete

        // Load K (transposed) and V (natural)
        #pragma unroll
        for (int u = 0; u < 16; u += 4) {
            float4 kk = *reinterpret_cast<const float4*>(kp + (size_t)(kbase + li) * HD + c0 + u);
            Kt[(c0 + u + 0) * 64 + li] = kk.x;
            Kt[(c0 + u + 1) * 64 + li] = kk.y;
            Kt[(c0 + u + 2) * 64 + li] = kk.z;
            Kt[(c0 + u + 3) * 64 + li] = kk.w;
            *reinterpret_cast<float4*>(&Vs[li * 64 + c0 + u]) =
                *reinterpret_cast<const float4*>(vp + (size_t)(kbase + li) * HD + c0 + u);
        }
        __syncthreads();

        // Phase A: S tile via FFMA2 (rows i = ty*4.. ; col pairs from Kt)
        {
            u64 acc2[4][2];
            #pragma unroll
            for (int i = 0; i < 4; i++) { acc2[i][0] = 0ull; acc2[i][1] = 0ull; }

            #pragma unroll 8
            for (int d = 0; d < HD; d++) {
                float4 qa = *reinterpret_cast<const float4*>(&Qt[d * 64 + ty * 4]);
                ulonglong2 kb = *reinterpret_cast<const ulonglong2*>(&Kt[d * 64 + tx * 4]);
                u64 a0 = dup2(qa.x), a1 = dup2(qa.y), a2 = dup2(qa.z), a3 = dup2(qa.w);
                ffma2(acc2[0][0], a0, kb.x); ffma2(acc2[0][1], a0, kb.y);
                ffma2(acc2[1][0], a1, kb.x); ffma2(acc2[1][1], a1, kb.y);
                ffma2(acc2[2][0], a2, kb.x); ffma2(acc2[2][1], a2, kb.y);
                ffma2(acc2[3][0], a3, kb.x); ffma2(acc2[3][1], a3, kb.y);
            }
            #pragma unroll
            for (int i = 0; i < 4; i++) {
                const int gi = qg0 + i;
                #pragma unroll
                for (int jp = 0; jp < 2; jp++) {
                    float2 v2 = unpk(acc2[i][jp]);
                    const int gj = kbase + tx * 4 + jp * 2;
                    Ss[(ty * 4 + i) * 65 + tx * 4 + jp * 2 + 0] =
                        (gj + 0 <= gi) ? v2.x * inv_scale : -1e30f;
                    Ss[(ty * 4 + i) * 65 + tx * 4 + jp * 2 + 1] =
                        (gj + 1 <= gi) ? v2.y * inv_scale : -1e30f;
                }
            }
        }
        __syncthreads();

        // Phase B: online softmax + O update (row li, dims c0..c0+15)
        float lmax = -1e30f;
        #pragma unroll
        for (int j = 0; j < 16; j++)
            lmax = fmaxf(lmax, Ss[li * 65 + c0 + j]);
        lmax = fmaxf(lmax, __shfl_xor_sync(0xffffffffu, lmax, 1));
        lmax = fmaxf(lmax, __shfl_xor_sync(0xffffffffu, lmax, 2));

        const float mnew = fmaxf(m, lmax);
        const float alpha = __expf(m - mnew);
        float lsum = 0.0f;
        #pragma unroll
        for (int j = 0; j < 16; j++) {
            const float p = __expf(Ss[li * 65 + c0 + j] - mnew);
            Ss[li * 65 + c0 + j] = p;
            lsum += p;
        }
        lsum += __shfl_xor_sync(0xffffffffu, lsum, 1);
        lsum += __shfl_xor_sync(0xffffffffu, lsum, 2);
        l = l * alpha + lsum;
        m = mnew;

        const u64 al2 = dup2(alpha);
        #pragma unroll
        for (int i = 0; i < 8; i++) o2[i] = fmul2(o2[i], al2);
        __syncwarp();   // p-writes to Ss row (split across the 4 group lanes) visible

        #pragma unroll 8
        for (int j = 0; j < 64; j++) {
            const u64 pd = dup2(Ss[li * 65 + j]);
            const ulonglong2* vrow = reinterpret_cast<const ulonglong2*>(&Vs[j * 64 + c0]);
            ulonglong2 v01 = vrow[0], v23 = vrow[1], v45 = vrow[2], v67 = vrow[3];
            ffma2(o2[0], pd, v01.x); ffma2(o2[1], pd, v01.y);
            ffma2(o2[2], pd, v23.x); ffma2(o2[3], pd, v23.y);
            ffma2(o2[4], pd, v45.x); ffma2(o2[5], pd, v45.y);
            ffma2(o2[6], pd, v67.x); ffma2(o2[7], pd, v67.y);
        }
    }

    // Normalize and store into [B,T,C] layout
    const u64 il2 = dup2(1.0f / l);
    const int b = bh >> 4, h = bh & (NH - 1);
    float* outp = g_att + (size_t)(b * T_SZ + qbase + li) * C_SZ + h * HD + c0;
    ulonglong2* op = reinterpret_cast<ulonglong2*>(outp);
    ulonglong2 w0, w1;
    w0.x = fmul2(o2[0], il2); w0.y = fmul2(o2[1], il2);
    w1.x = fmul2(o2[2], il2); w1.y = fmul2(o2[3], il2);
    op[0] = w0;
    op[1] = w1;
    w0.x = fmul2(o2[4], il2); w0.y = fmul2(o2[5], il2);
    w1.x = fmul2(o2[6], il2); w1.y = fmul2(o2[7], il2);
    op[2] = w0;
    op[3] = w1;
}

// ---------------------------------------------------------------------------
extern "C" void kernel_launch(void* const* d_in, const int* in_sizes, int n_in,
                              void* d_out, int out_size)
{
    const float* x     = (const float*)d_in[0];
    const float* Wqkv  = (const float*)d_in[1];
    const float* bqkv  = (const float*)d_in[2];
    const float* Wproj = (const float*)d_in[3];
    const float* bproj = (const float*)d_in[4];
    float* out = (float*)d_out;
    (void)in_sizes; (void)n_in; (void)out_size;

    cudaFuncSetAttribute(flash_attn, cudaFuncAttributeMaxDynamicSharedMemorySize,
                         FA_SMEM_BYTES);

    // 1) QKV projection + scatter to [B,H,T,hd]
    sgemm_bias<0><<<dim3(N_QKV / BN, M_ROWS / BM), 256>>>(
        x, Wqkv, bqkv, nullptr, M_ROWS, N_QKV, C_SZ);

    // 2) Causal flash attention -> g_att [B,T,C]
    flash_attn<<<dim3(T_SZ / 64, B_SZ * NH), 256, FA_SMEM_BYTES>>>();

    // 3) Output projection
    sgemm_bias<1><<<dim3(C_SZ / BN, M_ROWS / BM), 256>>>(
        nullptr, Wproj, bproj, out, M_ROWS, C_SZ, C_SZ);
}

// round 3
// speedup vs baseline: 1.0677x; 1.0677x over previous
#include <cuda_runtime.h>

// Problem constants
#define B_SZ 2
#define T_SZ 2048
#define C_SZ 1024
#define NH   16
#define HD   64
#define M_ROWS (B_SZ * T_SZ)     // 4096
#define N_QKV  (3 * C_SZ)        // 3072

typedef unsigned long long u64;

// Scratch (no allocations allowed -> __device__ globals)
__device__ float g_q[(size_t)B_SZ * NH * T_SZ * HD];   // [B,H,T,hd]
__device__ float g_k[(size_t)B_SZ * NH * T_SZ * HD];
__device__ float g_v[(size_t)B_SZ * NH * T_SZ * HD];
__device__ float g_att[(size_t)M_ROWS * C_SZ];         // [B,T,C]

// ---------------------------------------------------------------------------
// Packed f32x2 helpers (Blackwell). ptxas won't auto-fuse from C++.
// ---------------------------------------------------------------------------
__device__ __forceinline__ u64 dup2(float a) {
    u64 r; asm("mov.b64 %0, {%1, %1};" : "=l"(r) : "f"(a)); return r;
}
__device__ __forceinline__ void ffma2(u64 &c, u64 a, u64 b) {
    asm("fma.rn.f32x2 %0, %1, %2, %0;" : "+l"(c) : "l"(a), "l"(b));
}
__device__ __forceinline__ u64 fmul2(u64 a, u64 b) {
    u64 r; asm("mul.rn.f32x2 %0, %1, %2;" : "=l"(r) : "l"(a), "l"(b)); return r;
}
__device__ __forceinline__ u64 fadd2(u64 a, u64 b) {
    u64 r; asm("add.rn.f32x2 %0, %1, %2;" : "=l"(r) : "l"(a), "l"(b)); return r;
}
__device__ __forceinline__ float2 unpk(u64 v) {
    float2 r; asm("mov.b64 {%0, %1}, %2;" : "=f"(r.x), "=f"(r.y) : "l"(v)); return r;
}

// ---------------------------------------------------------------------------
// SGEMM: C = A @ B + bias, 128x128 tile, BK=8, 8x8/thread, 256 thr.
// R1 memory structure (single-buffer smem, identical LDS addresses) but
// FFMA2 paired over j: B pairs come straight from LDS.128 (consecutive j),
// A stays scalar and is duplicated in REGISTERS (mov, alu pipe).
// Inner loop per kk: 4 LDS.128 + 8 mov + 32 FFMA2  (R1: 4 LDS.128 + 64 FFMA)
// MODE 0: A = x, epilogue scatters qkv into g_q/g_k/g_v ([B,H,T,hd])
// MODE 1: A = g_att, epilogue writes Cout row-major
// ---------------------------------------------------------------------------
#define BM 128
#define BN 128
#define BK 8

template <int MODE>
__global__ __launch_bounds__(256, 2)
void sgemm_bias(const float* __restrict__ A,
                const float* __restrict__ Bmat,
                const float* __restrict__ bias,
                float* __restrict__ Cout,
                int M, int N, int K)
{
    __shared__ float As[BK][BM];
    __shared__ float Bs[BK][BN];

    const int tid = threadIdx.x;
    const int bx = blockIdx.x, by = blockIdx.y;

    const float* Ap = (MODE == 1) ? g_att : A;

    const int rowA = tid >> 1;
    const int colA = (tid & 1) * 4;
    const int rowB = tid >> 5;
    const int colB = (tid & 31) * 4;

    const float* Abase = Ap + (size_t)(by * BM) * K;
    const float* Bbase = Bmat + (size_t)(bx * BN);

    const int tx = tid & 15;
    const int ty = tid >> 4;

    u64 acc[8][4];
    #pragma unroll
    for (int i = 0; i < 8; i++)
        #pragma unroll
        for (int j = 0; j < 4; j++)
            acc[i][j] = 0ull;

    for (int k0 = 0; k0 < K; k0 += BK) {
        float4 a4 = *reinterpret_cast<const float4*>(Abase + (size_t)rowA * K + k0 + colA);
        As[colA + 0][rowA] = a4.x;
        As[colA + 1][rowA] = a4.y;
        As[colA + 2][rowA] = a4.z;
        As[colA + 3][rowA] = a4.w;
        *reinterpret_cast<float4*>(&Bs[rowB][colB]) =
            *reinterpret_cast<const float4*>(Bbase + (size_t)(k0 + rowB) * N + colB);
        __syncthreads();

        #pragma unroll
        for (int kk = 0; kk < BK; kk++) {
            float4 a0 = *reinterpret_cast<const float4*>(&As[kk][ty * 8]);
            float4 a1 = *reinterpret_cast<const float4*>(&As[kk][ty * 8 + 4]);
            ulonglong2 b01 = *reinterpret_cast<const ulonglong2*>(&Bs[kk][tx * 8]);
            ulonglong2 b23 = *reinterpret_cast<const ulonglong2*>(&Bs[kk][tx * 8 + 4]);
            u64 rb[4] = {b01.x, b01.y, b23.x, b23.y};
            u64 ra[8] = {dup2(a0.x), dup2(a0.y), dup2(a0.z), dup2(a0.w),
                         dup2(a1.x), dup2(a1.y), dup2(a1.z), dup2(a1.w)};
            #pragma unroll
            for (int i = 0; i < 8; i++)
                #pragma unroll
                for (int j = 0; j < 4; j++)
                    ffma2(acc[i][j], ra[i], rb[j]);
        }
        __syncthreads();
    }

    const int mbase = by * BM + ty * 8;
    const int nbase = bx * BN + tx * 8;

    if (MODE == 0) {
        // n -> head h = n/192, inner = n%192 ; inner<64 -> q, <128 -> k, else v
        #pragma unroll
        for (int jp = 0; jp < 4; jp++) {
            #pragma unroll
            for (int jl = 0; jl < 2; jl++) {
                const int n = nbase + jp * 2 + jl;
                const int h = n / 192;
                const int inner = n - h * 192;
                const int which = inner >> 6;
                const int d = inner & 63;
                const float bv = bias[n];
                float* dst = (which == 0) ? g_q : (which == 1) ? g_k : g_v;
                #pragma unroll
                for (int i = 0; i < 8; i++) {
                    const int mm = mbase + i;
                    const int b = mm >> 11;           // /2048
                    const int t = mm & (T_SZ - 1);
                    float2 v2 = unpk(acc[i][jp]);
                    dst[(((size_t)(b * NH + h) * T_SZ + t) * HD) + d] =
                        ((jl == 0) ? v2.x : v2.y) + bv;
                }
            }
        }
    } else {
        const ulonglong2* bb = reinterpret_cast<const ulonglong2*>(&bias[nbase]);
        ulonglong2 bb0 = bb[0], bb1 = bb[1];
        #pragma unroll
        for (int i = 0; i < 8; i++) {
            const int mm = mbase + i;
            ulonglong2 s0, s1;
            s0.x = fadd2(acc[i][0], bb0.x);
            s0.y = fadd2(acc[i][1], bb0.y);
            s1.x = fadd2(acc[i][2], bb1.x);
            s1.y = fadd2(acc[i][3], bb1.y);
            ulonglong2* op = reinterpret_cast<ulonglong2*>(&Cout[(size_t)mm * N + nbase]);
            op[0] = s0;
            op[1] = s1;
        }
    }
}

// ---------------------------------------------------------------------------
// Causal flash attention. grid = (T/64, B*NH), 256 threads, 2 CTAs/SM.
// Double-buffered K/V smem: K[kt+1] prefetched (LDG early, STS after compute)
// inside phase A, V[kt+1] inside phase B. 2 syncthreads per k-tile, no
// exposed gmem latency in steady state. qtile order reversed (heavy first).
// smem: Qt[64][64] + Kt2[2][64][64] + Vs2[2][64][64] + Ss[64][65]
// ---------------------------------------------------------------------------
#define FA_SMEM_FLOATS (64*64 + 2*64*64 + 2*64*64 + 64*65)
#define FA_SMEM_BYTES  (FA_SMEM_FLOATS * 4)

__global__ __launch_bounds__(256, 2)
void flash_attn()
{
    extern __shared__ float sm[];
    float* Qt  = sm;                      // [d][i]
    float* Kt2 = sm + 64 * 64;            // [2][d][j]
    float* Vs2 = sm + 3 * 64 * 64;        // [2][j][d]
    float* Ss  = sm + 5 * 64 * 64;        // [i][j], ld 65

    const int tid = threadIdx.x;
    const int bh = blockIdx.y;                         // b*NH + h
    const int qtile = gridDim.x - 1 - blockIdx.x;      // heavy tiles first
    const int qbase = qtile * 64;
    const size_t base = (size_t)bh * T_SZ * HD;
    const float* qp = g_q + base;
    const float* kp = g_k + base;
    const float* vp = g_v + base;

    const int li = tid >> 2;        // row 0..63
    const int c0 = (tid & 3) * 16;  // 16-wide chunk

    // Load Q (transposed) + K0 (transposed) + V0 (natural)
    #pragma unroll
    for (int u = 0; u < 16; u += 4) {
        float4 v4 = *reinterpret_cast<const float4*>(qp + (size_t)(qbase + li) * HD + c0 + u);
        Qt[(c0 + u + 0) * 64 + li] = v4.x;
        Qt[(c0 + u + 1) * 64 + li] = v4.y;
        Qt[(c0 + u + 2) * 64 + li] = v4.z;
        Qt[(c0 + u + 3) * 64 + li] = v4.w;
        float4 kk = *reinterpret_cast<const float4*>(kp + (size_t)li * HD + c0 + u);
        Kt2[(c0 + u + 0) * 64 + li] = kk.x;
        Kt2[(c0 + u + 1) * 64 + li] = kk.y;
        Kt2[(c0 + u + 2) * 64 + li] = kk.z;
        Kt2[(c0 + u + 3) * 64 + li] = kk.w;
        *reinterpret_cast<float4*>(&Vs2[li * 64 + c0 + u]) =
            *reinterpret_cast<const float4*>(vp + (size_t)li * HD + c0 + u);
    }
    __syncthreads();

    const int tx = tid & 15;
    const int ty = tid >> 4;
    const int qg0 = qbase + ty * 4;

    float m = -1e30f, l = 0.0f;
    u64 o2[8];
    #pragma unroll
    for (int i = 0; i < 8; i++) o2[i] = 0ull;
    const float inv_scale = 0.125f;  // 1/sqrt(64)

    const int ntiles = qtile + 1;
    for (int kt = 0; kt < ntiles; kt++) {
        const int cur = kt & 1;
        const int nxt = cur ^ 1;
        const bool has_next = (kt + 1 < ntiles);
        const float* Kt = Kt2 + cur * 4096;
        const float* Vs = Vs2 + cur * 4096;

        // ---- prefetch K[kt+1] into regs (latency hidden under phase A) ----
        float4 kr0, kr1, kr2, kr3;
        if (has_next) {
            const float* kn = kp + (size_t)((kt + 1) * 64 + li) * HD + c0;
            kr0 = *reinterpret_cast<const float4*>(kn + 0);
            kr1 = *reinterpret_cast<const float4*>(kn + 4);
            kr2 = *reinterpret_cast<const float4*>(kn + 8);
            kr3 = *reinterpret_cast<const float4*>(kn + 12);
        }

        // ---- Phase A: S = Q K^T / 8 (FFMA2, pairs over j) ----
        {
            u64 acc2[4][2];
            #pragma unroll
            for (int i = 0; i < 4; i++) { acc2[i][0] = 0ull; acc2[i][1] = 0ull; }

            #pragma unroll 8
            for (int d = 0; d < HD; d++) {
                float4 qa = *reinterpret_cast<const float4*>(&Qt[d * 64 + ty * 4]);
                ulonglong2 kb = *reinterpret_cast<const ulonglong2*>(&Kt[d * 64 + tx * 4]);
                u64 a0 = dup2(qa.x), a1 = dup2(qa.y), a2 = dup2(qa.z), a3 = dup2(qa.w);
                ffma2(acc2[0][0], a0, kb.x); ffma2(acc2[0][1], a0, kb.y);
                ffma2(acc2[1][0], a1, kb.x); ffma2(acc2[1][1], a1, kb.y);
                ffma2(acc2[2][0], a2, kb.x); ffma2(acc2[2][1], a2, kb.y);
                ffma2(acc2[3][0], a3, kb.x); ffma2(acc2[3][1], a3, kb.y);
            }
            const int kbase = kt * 64;
            #pragma unroll
            for (int i = 0; i < 4; i++) {
                const int gi = qg0 + i;
                #pragma unroll
                for (int jp = 0; jp < 2; jp++) {
                    float2 v2 = unpk(acc2[i][jp]);
                    const int gj = kbase + tx * 4 + jp * 2;
                    Ss[(ty * 4 + i) * 65 + tx * 4 + jp * 2 + 0] =
                        (gj + 0 <= gi) ? v2.x * inv_scale : -1e30f;
                    Ss[(ty * 4 + i) * 65 + tx * 4 + jp * 2 + 1] =
                        (gj + 1 <= gi) ? v2.y * inv_scale : -1e30f;
                }
            }
        }

        // ---- store prefetched K (transposed) into next buffer ----
        if (has_next) {
            float* Kn = Kt2 + nxt * 4096;
            Kn[(c0 + 0) * 64 + li] = kr0.x;  Kn[(c0 + 1) * 64 + li] = kr0.y;
            Kn[(c0 + 2) * 64 + li] = kr0.z;  Kn[(c0 + 3) * 64 + li] = kr0.w;
            Kn[(c0 + 4) * 64 + li] = kr1.x;  Kn[(c0 + 5) * 64 + li] = kr1.y;
            Kn[(c0 + 6) * 64 + li] = kr1.z;  Kn[(c0 + 7) * 64 + li] = kr1.w;
            Kn[(c0 + 8) * 64 + li] = kr2.x;  Kn[(c0 + 9) * 64 + li] = kr2.y;
            Kn[(c0 +10) * 64 + li] = kr2.z;  Kn[(c0 +11) * 64 + li] = kr2.w;
            Kn[(c0 +12) * 64 + li] = kr3.x;  Kn[(c0 +13) * 64 + li] = kr3.y;
            Kn[(c0 +14) * 64 + li] = kr3.z;  Kn[(c0 +15) * 64 + li] = kr3.w;
        }
        __syncthreads();   // Ss + K[nxt] visible

        // ---- prefetch V[kt+1] into regs (latency hidden under phase B) ----
        float4 vr0, vr1, vr2, vr3;
        if (has_next) {
            const float* vn = vp + (size_t)((kt + 1) * 64 + li) * HD + c0;
            vr0 = *reinterpret_cast<const float4*>(vn + 0);
            vr1 = *reinterpret_cast<const float4*>(vn + 4);
            vr2 = *reinterpret_cast<const float4*>(vn + 8);
            vr3 = *reinterpret_cast<const float4*>(vn + 12);
        }

        // ---- Phase B: online softmax + O update ----
        float lmax = -1e30f;
        #pragma unroll
        for (int j = 0; j < 16; j++)
            lmax = fmaxf(lmax, Ss[li * 65 + c0 + j]);
        lmax = fmaxf(lmax, __shfl_xor_sync(0xffffffffu, lmax, 1));
        lmax = fmaxf(lmax, __shfl_xor_sync(0xffffffffu, lmax, 2));

        const float mnew = fmaxf(m, lmax);
        const float alpha = __expf(m - mnew);
        float lsum = 0.0f;
        #pragma unroll
        for (int j = 0; j < 16; j++) {
            const float p = __expf(Ss[li * 65 + c0 + j] - mnew);
            Ss[li * 65 + c0 + j] = p;
            lsum += p;
        }
        lsum += __shfl_xor_sync(0xffffffffu, lsum, 1);
        lsum += __shfl_xor_sync(0xffffffffu, lsum, 2);
        l = l * alpha + lsum;
        m = mnew;

        const u64 al2 = dup2(alpha);
        #pragma unroll
        for (int i = 0; i < 8; i++) o2[i] = fmul2(o2[i], al2);
        __syncwarp();   // p-writes to Ss row (split across 4 lanes) visible

        #pragma unroll 8
        for (int j = 0; j < 64; j++) {
            const u64 pd = dup2(Ss[li * 65 + j]);
            const ulonglong2* vrow = reinterpret_cast<const ulonglong2*>(&Vs[j * 64 + c0]);
            ulonglong2 v01 = vrow[0], v23 = vrow[1], v45 = vrow[2], v67 = vrow[3];
            ffma2(o2[0], pd, v01.x); ffma2(o2[1], pd, v01.y);
            ffma2(o2[2], pd, v23.x); ffma2(o2[3], pd, v23.y);
            ffma2(o2[4], pd, v45.x); ffma2(o2[5], pd, v45.y);
            ffma2(o2[6], pd, v67.x); ffma2(o2[7], pd, v67.y);
        }

        // ---- store prefetched V (natural) into next buffer ----
        if (has_next) {
            float* Vn = Vs2 + nxt * 4096 + li * 64 + c0;
            *reinterpret_cast<float4*>(Vn + 0)  = vr0;
            *reinterpret_cast<float4*>(Vn + 4)  = vr1;
            *reinterpret_cast<float4*>(Vn + 8)  = vr2;
            *reinterpret_cast<float4*>(Vn + 12) = vr3;
        }
        __syncthreads();   // Ss free to rewrite; V[nxt] visible
    }

    // Normalize and store into [B,T,C] layout
    const u64 il2 = dup2(1.0f / l);
    const int b = bh >> 4, h = bh & (NH - 1);
    float* outp = g_att + (size_t)(b * T_SZ + qbase + li) * C_SZ + h * HD + c0;
    ulonglong2* op = reinterpret_cast<ulonglong2*>(outp);
    ulonglong2 w0, w1;
    w0.x = fmul2(o2[0], il2); w0.y = fmul2(o2[1], il2);
    w1.x = fmul2(o2[2], il2); w1.y = fmul2(o2[3], il2);
    op[0] = w0;
    op[1] = w1;
    w0.x = fmul2(o2[4], il2); w0.y = fmul2(o2[5], il2);
    w1.x = fmul2(o2[6], il2); w1.y = fmul2(o2[7], il2);
    op[2] = w0;
    op[3] = w1;
}

// ---------------------------------------------------------------------------
extern "C" void kernel_launch(void* const* d_in, const int* in_sizes, int n_in,
                              void* d_out, int out_size)
{
    const float* x     = (const float*)d_in[0];
    const float* Wqkv  = (const float*)d_in[1];
    const float* bqkv  = (const float*)d_in[2];
    const float* Wproj = (const float*)d_in[3];
    const float* bproj = (const float*)d_in[4];
    float* out = (float*)d_out;
    (void)in_sizes; (void)n_in; (void)out_size;

    cudaFuncSetAttribute(flash_attn, cudaFuncAttributeMaxDynamicSharedMemorySize,
                         FA_SMEM_BYTES);

    // 1) QKV projection + scatter to [B,H,T,hd]
    sgemm_bias<0><<<dim3(N_QKV / BN, M_ROWS / BM), 256>>>(
        x, Wqkv, bqkv, nullptr, M_ROWS, N_QKV, C_SZ);

    // 2) Causal flash attention -> g_att [B,T,C]
    flash_attn<<<dim3(T_SZ / 64, B_SZ * NH), 256, FA_SMEM_BYTES>>>();

    // 3) Output projection
    sgemm_bias<1><<<dim3(C_SZ / BN, M_ROWS / BM), 256>>>(
        nullptr, Wproj, bproj, out, M_ROWS, C_SZ, C_SZ);
}

// round 12
// speedup vs baseline: 1.0758x; 1.0076x over previous
#include <cuda_runtime.h>
#include <cstdint>

// Problem constants
#define B_SZ 2
#define T_SZ 2048
#define C_SZ 1024
#define NH   16
#define HD   64
#define M_ROWS (B_SZ * T_SZ)     // 4096
#define N_QKV  (3 * C_SZ)        // 3072

typedef unsigned long long u64;

// Scratch (no allocations allowed -> __device__ globals)
__device__ float g_q[(size_t)B_SZ * NH * T_SZ * HD];   // [B,H,T,hd]
__device__ float g_k[(size_t)B_SZ * NH * T_SZ * HD];
__device__ float g_v[(size_t)B_SZ * NH * T_SZ * HD];
__device__ float g_att[(size_t)M_ROWS * C_SZ];         // [B,T,C]

// ---------------------------------------------------------------------------
// Packed f32x2 helpers (proven)
// ---------------------------------------------------------------------------
__device__ __forceinline__ u64 dup2(float a) {
    u64 r; asm("mov.b64 %0, {%1, %1};" : "=l"(r) : "f"(a)); return r;
}
__device__ __forceinline__ void ffma2(u64 &c, u64 a, u64 b) {
    asm("fma.rn.f32x2 %0, %1, %2, %0;" : "+l"(c) : "l"(a), "l"(b));
}
__device__ __forceinline__ u64 fmul2(u64 a, u64 b) {
    u64 r; asm("mul.rn.f32x2 %0, %1, %2;" : "=l"(r) : "l"(a), "l"(b)); return r;
}
__device__ __forceinline__ u64 fadd2(u64 a, u64 b) {
    u64 r; asm("add.rn.f32x2 %0, %1, %2;" : "=l"(r) : "l"(a), "l"(b)); return r;
}
__device__ __forceinline__ float2 unpk(u64 v) {
    float2 r; asm("mov.b64 {%0, %1}, %2;" : "=f"(r.x), "=f"(r.y) : "l"(v)); return r;
}

// ---------------------------------------------------------------------------
// PROVEN R3 SGEMM (FFMA2 over j): QKV projection + scatter epilogue.
// ---------------------------------------------------------------------------
#define BM 128
#define BN 128
#define BK 8

__global__ __launch_bounds__(256, 2)
void sgemm_qkv(const float* __restrict__ A,
               const float* __restrict__ Bmat,
               const float* __restrict__ bias,
               int M, int N, int K)
{
    __shared__ float As[BK][BM];
    __shared__ float Bs[BK][BN];

    const int tid = threadIdx.x;
    const int bx = blockIdx.x, by = blockIdx.y;

    const int rowA = tid >> 1;
    const int colA = (tid & 1) * 4;
    const int rowB = tid >> 5;
    const int colB = (tid & 31) * 4;

    const float* Abase = A + (size_t)(by * BM) * K;
    const float* Bbase = Bmat + (size_t)(bx * BN);

    const int tx = tid & 15;
    const int ty = tid >> 4;

    u64 acc[8][4];
    #pragma unroll
    for (int i = 0; i < 8; i++)
        #pragma unroll
        for (int j = 0; j < 4; j++)
            acc[i][j] = 0ull;

    for (int k0 = 0; k0 < K; k0 += BK) {
        float4 a4 = *reinterpret_cast<const float4*>(Abase + (size_t)rowA * K + k0 + colA);
        As[colA + 0][rowA] = a4.x;
        As[colA + 1][rowA] = a4.y;
        As[colA + 2][rowA] = a4.z;
        As[colA + 3][rowA] = a4.w;
        *reinterpret_cast<float4*>(&Bs[rowB][colB]) =
            *reinterpret_cast<const float4*>(Bbase + (size_t)(k0 + rowB) * N + colB);
        __syncthreads();

        #pragma unroll
        for (int kk = 0; kk < BK; kk++) {
            float4 a0 = *reinterpret_cast<const float4*>(&As[kk][ty * 8]);
            float4 a1 = *reinterpret_cast<const float4*>(&As[kk][ty * 8 + 4]);
            ulonglong2 b01 = *reinterpret_cast<const ulonglong2*>(&Bs[kk][tx * 8]);
            ulonglong2 b23 = *reinterpret_cast<const ulonglong2*>(&Bs[kk][tx * 8 + 4]);
            u64 rb[4] = {b01.x, b01.y, b23.x, b23.y};
            u64 ra[8] = {dup2(a0.x), dup2(a0.y), dup2(a0.z), dup2(a0.w),
                         dup2(a1.x), dup2(a1.y), dup2(a1.z), dup2(a1.w)};
            #pragma unroll
            for (int i = 0; i < 8; i++)
                #pragma unroll
                for (int j = 0; j < 4; j++)
                    ffma2(acc[i][j], ra[i], rb[j]);
        }
        __syncthreads();
    }

    const int mbase = by * BM + ty * 8;
    const int nbase = bx * BN + tx * 8;

    #pragma unroll
    for (int jp = 0; jp < 4; jp++) {
        #pragma unroll
        for (int jl = 0; jl < 2; jl++) {
            const int n = nbase + jp * 2 + jl;
            const int h = n / 192;
            const int inner = n - h * 192;
            const int which = inner >> 6;
            const int d = inner & 63;
            const float bv = bias[n];
            float* dst = (which == 0) ? g_q : (which == 1) ? g_k : g_v;
            #pragma unroll
            for (int i = 0; i < 8; i++) {
                const int mm = mbase + i;
                const int b = mm >> 11;
                const int t = mm & (T_SZ - 1);
                float2 v2 = unpk(acc[i][jp]);
                dst[(((size_t)(b * NH + h) * T_SZ + t) * HD) + d] =
                    ((jl == 0) ? v2.x : v2.y) + bv;
            }
        }
    }
}

// ---------------------------------------------------------------------------
// PROVEN R3 SGEMM (MODE 1): output projection, row-major epilogue.
// ---------------------------------------------------------------------------
__global__ __launch_bounds__(256, 2)
void sgemm_proj(const float* __restrict__ Bmat,
                const float* __restrict__ bias,
                float* __restrict__ Cout,
                int M, int N, int K)
{
    __shared__ float As[BK][BM];
    __shared__ float Bs[BK][BN];

    const int tid = threadIdx.x;
    const int bx = blockIdx.x, by = blockIdx.y;

    const int rowA = tid >> 1;
    const int colA = (tid & 1) * 4;
    const int rowB = tid >> 5;
    const int colB = (tid & 31) * 4;

    const float* Abase = g_att + (size_t)(by * BM) * K;
    const float* Bbase = Bmat + (size_t)(bx * BN);

    const int tx = tid & 15;
    const int ty = tid >> 4;

    u64 acc[8][4];
    #pragma unroll
    for (int i = 0; i < 8; i++)
        #pragma unroll
        for (int j = 0; j < 4; j++)
            acc[i][j] = 0ull;

    for (int k0 = 0; k0 < K; k0 += BK) {
        float4 a4 = *reinterpret_cast<const float4*>(Abase + (size_t)rowA * K + k0 + colA);
        As[colA + 0][rowA] = a4.x;
        As[colA + 1][rowA] = a4.y;
        As[colA + 2][rowA] = a4.z;
        As[colA + 3][rowA] = a4.w;
        *reinterpret_cast<float4*>(&Bs[rowB][colB]) =
            *reinterpret_cast<const float4*>(Bbase + (size_t)(k0 + rowB) * N + colB);
        __syncthreads();

        #pragma unroll
        for (int kk = 0; kk < BK; kk++) {
            float4 a0 = *reinterpret_cast<const float4*>(&As[kk][ty * 8]);
            float4 a1 = *reinterpret_cast<const float4*>(&As[kk][ty * 8 + 4]);
            ulonglong2 b01 = *reinterpret_cast<const ulonglong2*>(&Bs[kk][tx * 8]);
            ulonglong2 b23 = *reinterpret_cast<const ulonglong2*>(&Bs[kk][tx * 8 + 4]);
            u64 rb[4] = {b01.x, b01.y, b23.x, b23.y};
            u64 ra[8] = {dup2(a0.x), dup2(a0.y), dup2(a0.z), dup2(a0.w),
                         dup2(a1.x), dup2(a1.y), dup2(a1.z), dup2(a1.w)};
            #pragma unroll
            for (int i = 0; i < 8; i++)
                #pragma unroll
                for (int j = 0; j < 4; j++)
                    ffma2(acc[i][j], ra[i], rb[j]);
        }
        __syncthreads();
    }

    const int mbase = by * BM + ty * 8;
    const int nbase = bx * BN + tx * 8;

    const ulonglong2* bb = reinterpret_cast<const ulonglong2*>(&bias[nbase]);
    ulonglong2 bb0 = bb[0], bb1 = bb[1];
    #pragma unroll
    for (int i = 0; i < 8; i++) {
        const int mm = mbase + i;
        ulonglong2 s0, s1;
        s0.x = fadd2(acc[i][0], bb0.x);
        s0.y = fadd2(acc[i][1], bb0.y);
        s1.x = fadd2(acc[i][2], bb1.x);
        s1.y = fadd2(acc[i][3], bb1.y);
        ulonglong2* op = reinterpret_cast<ulonglong2*>(&Cout[(size_t)mm * N + nbase]);
        op[0] = s0;
        op[1] = s1;
    }
}

// ---------------------------------------------------------------------------
// Causal flash attention v2: register-resident softmax.
// grid = (T/64, B*NH), 256 threads, 2 CTAs/SM.
// Phase A computes S in regs (16x16 thread grid, 4x4 each), masks/scales in
// regs, reduces row max/sum via 4-stage shfl.bfly across the row's 16 lanes,
// applies exp in regs, stores P via STS.128. alpha / final-l handed to the
// PV mapping through a small smem buffer. K/V double-buffered with register
// prefetch (R3 structure). 2 syncthreads per k-tile, no syncwarp.
// smem: Qt[64][64] | Kt2[2][64][64] | Vs2[2][64][64] | Ss[64][68] | alf[128]
// ---------------------------------------------------------------------------
#define FA_SS 68
#define FA_SMEM_FLOATS (64*64 + 2*64*64 + 2*64*64 + 64*FA_SS + 128)
#define FA_SMEM_BYTES  (FA_SMEM_FLOATS * 4)

#define FA_PV(PP, JJ) do {                                                     \
    const u64 pd = dup2(PP);                                                   \
    const ulonglong2* vrow =                                                   \
        reinterpret_cast<const ulonglong2*>(&Vs[(JJ) * 64 + c0]);              \
    ulonglong2 v01 = vrow[0], v23 = vrow[1], v45 = vrow[2], v67 = vrow[3];     \
    ffma2(o2[0], pd, v01.x); ffma2(o2[1], pd, v01.y);                          \
    ffma2(o2[2], pd, v23.x); ffma2(o2[3], pd, v23.y);                          \
    ffma2(o2[4], pd, v45.x); ffma2(o2[5], pd, v45.y);                          \
    ffma2(o2[6], pd, v67.x); ffma2(o2[7], pd, v67.y);                          \
} while (0)

__global__ __launch_bounds__(256, 2)
void flash_attn()
{
    extern __shared__ float sm[];
    float* Qt  = sm;                      // [d][i]
    float* Kt2 = sm + 4096;               // [2][d][j]
    float* Vs2 = sm + 12288;              // [2][j][d]
    float* Ss  = sm + 20480;              // [i][j], ld FA_SS
    float* alf = sm + 20480 + 64 * FA_SS; // [0:64) alpha per row, [64:128) final l

    const int tid = threadIdx.x;
    const int bh = blockIdx.y;
    const int qtile = gridDim.x - 1 - blockIdx.x;      // heavy tiles first
    const int qbase = qtile * 64;
    const size_t base = (size_t)bh * T_SZ * HD;
    const float* qp = g_q + base;
    const float* kp = g_k + base;
    const float* vp = g_v + base;

    const int li = tid >> 2;        // PV row
    const int c0 = (tid & 3) * 16;  // PV dim chunk / loader chunk

    // Prologue: load Q (transposed), K0 (transposed), V0 (natural)
    #pragma unroll
    for (int u = 0; u < 16; u += 4) {
        float4 v4 = *reinterpret_cast<const float4*>(qp + (size_t)(qbase + li) * HD + c0 + u);
        Qt[(c0 + u + 0) * 64 + li] = v4.x;
        Qt[(c0 + u + 1) * 64 + li] = v4.y;
        Qt[(c0 + u + 2) * 64 + li] = v4.z;
        Qt[(c0 + u + 3) * 64 + li] = v4.w;
        float4 kk = *reinterpret_cast<const float4*>(kp + (size_t)li * HD + c0 + u);
        Kt2[(c0 + u + 0) * 64 + li] = kk.x;
        Kt2[(c0 + u + 1) * 64 + li] = kk.y;
        Kt2[(c0 + u + 2) * 64 + li] = kk.z;
        Kt2[(c0 + u + 3) * 64 + li] = kk.w;
        *reinterpret_cast<float4*>(&Vs2[li * 64 + c0 + u]) =
            *reinterpret_cast<const float4*>(vp + (size_t)li * HD + c0 + u);
    }
    __syncthreads();

    const int tx = tid & 15;        // phase-A col group (4 cols)
    const int ty = tid >> 4;        // phase-A row group (4 rows)
    const int qg0 = qbase + ty * 4;

    float m[4], l[4];
    #pragma unroll
    for (int i = 0; i < 4; i++) { m[i] = -1e30f; l[i] = 0.0f; }
    u64 o2[8];
    #pragma unroll
    for (int i = 0; i < 8; i++) o2[i] = 0ull;
    const float inv_scale = 0.125f;  // 1/sqrt(64)

    const int ntiles = qtile + 1;
    for (int kt = 0; kt < ntiles; kt++) {
        const int cur = kt & 1;
        const int nxt = cur ^ 1;
        const bool hn = (kt + 1 < ntiles);
        const float* Kt = Kt2 + cur * 4096;
        const float* Vs = Vs2 + cur * 4096;

        // prefetch K[kt+1] (latency hidden under phase A)
        float4 kr0, kr1, kr2, kr3;
        if (hn) {
            const float* kn = kp + (size_t)((kt + 1) * 64 + li) * HD + c0;
            kr0 = *reinterpret_cast<const float4*>(kn + 0);
            kr1 = *reinterpret_cast<const float4*>(kn + 4);
            kr2 = *reinterpret_cast<const float4*>(kn + 8);
            kr3 = *reinterpret_cast<const float4*>(kn + 12);
        }

        // ---- Phase A: S = Q K^T (FFMA2, pairs over j) ----
        u64 acc2[4][2];
        #pragma unroll
        for (int i = 0; i < 4; i++) { acc2[i][0] = 0ull; acc2[i][1] = 0ull; }

        #pragma unroll 8
        for (int d = 0; d < HD; d++) {
            float4 qa = *reinterpret_cast<const float4*>(&Qt[d * 64 + ty * 4]);
            ulonglong2 kb = *reinterpret_cast<const ulonglong2*>(&Kt[d * 64 + tx * 4]);
            u64 a0 = dup2(qa.x), a1 = dup2(qa.y), a2 = dup2(qa.z), a3 = dup2(qa.w);
            ffma2(acc2[0][0], a0, kb.x); ffma2(acc2[0][1], a0, kb.y);
            ffma2(acc2[1][0], a1, kb.x); ffma2(acc2[1][1], a1, kb.y);
            ffma2(acc2[2][0], a2, kb.x); ffma2(acc2[2][1], a2, kb.y);
            ffma2(acc2[3][0], a3, kb.x); ffma2(acc2[3][1], a3, kb.y);
        }

        // mask + scale into registers
        const int kbase = kt * 64;
        float4 pr[4];
        #pragma unroll
        for (int i = 0; i < 4; i++) {
            float2 va = unpk(acc2[i][0]);
            float2 vb = unpk(acc2[i][1]);
            const int gi = qg0 + i;
            const int gb = kbase + tx * 4;
            pr[i].x = (gb + 0 <= gi) ? va.x * inv_scale : -1e30f;
            pr[i].y = (gb + 1 <= gi) ? va.y * inv_scale : -1e30f;
            pr[i].z = (gb + 2 <= gi) ? vb.x * inv_scale : -1e30f;
            pr[i].w = (gb + 3 <= gi) ? vb.y * inv_scale : -1e30f;
        }

        // store prefetched K (transposed) -> next buffer (frees kr regs)
        if (hn) {
            float* Kn = Kt2 + nxt * 4096;
            Kn[(c0 + 0) * 64 + li] = kr0.x;  Kn[(c0 + 1) * 64 + li] = kr0.y;
            Kn[(c0 + 2) * 64 + li] = kr0.z;  Kn[(c0 + 3) * 64 + li] = kr0.w;
            Kn[(c0 + 4) * 64 + li] = kr1.x;  Kn[(c0 + 5) * 64 + li] = kr1.y;
            Kn[(c0 + 6) * 64 + li] = kr1.z;  Kn[(c0 + 7) * 64 + li] = kr1.w;
            Kn[(c0 + 8) * 64 + li] = kr2.x;  Kn[(c0 + 9) * 64 + li] = kr2.y;
            Kn[(c0 +10) * 64 + li] = kr2.z;  Kn[(c0 +11) * 64 + li] = kr2.w;
            Kn[(c0 +12) * 64 + li] = kr3.x;  Kn[(c0 +13) * 64 + li] = kr3.y;
            Kn[(c0 +14) * 64 + li] = kr3.z;  Kn[(c0 +15) * 64 + li] = kr3.w;
        }

        // ---- register softmax: row max over 16 lanes ----
        float rmax[4];
        #pragma unroll
        for (int i = 0; i < 4; i++)
            rmax[i] = fmaxf(fmaxf(pr[i].x, pr[i].y), fmaxf(pr[i].z, pr[i].w));
        #pragma unroll
        for (int st = 1; st < 16; st <<= 1) {
            #pragma unroll
            for (int i = 0; i < 4; i++)
                rmax[i] = fmaxf(rmax[i], __shfl_xor_sync(0xffffffffu, rmax[i], st));
        }

        float alpha[4];
        #pragma unroll
        for (int i = 0; i < 4; i++) {
            const float mn = fmaxf(m[i], rmax[i]);
            alpha[i] = __expf(m[i] - mn);
            m[i] = mn;
        }
        #pragma unroll
        for (int i = 0; i < 4; i++) {
            pr[i].x = __expf(pr[i].x - m[i]);
            pr[i].y = __expf(pr[i].y - m[i]);
            pr[i].z = __expf(pr[i].z - m[i]);
            pr[i].w = __expf(pr[i].w - m[i]);
        }

        float rsum[4];
        #pragma unroll
        for (int i = 0; i < 4; i++)
            rsum[i] = (pr[i].x + pr[i].y) + (pr[i].z + pr[i].w);
        #pragma unroll
        for (int st = 1; st < 16; st <<= 1) {
            #pragma unroll
            for (int i = 0; i < 4; i++)
                rsum[i] += __shfl_xor_sync(0xffffffffu, rsum[i], st);
        }
        #pragma unroll
        for (int i = 0; i < 4; i++)
            l[i] = l[i] * alpha[i] + rsum[i];

        // store P rows (STS.128) + alpha (+ final l on last tile)
        #pragma unroll
        for (int i = 0; i < 4; i++)
            *reinterpret_cast<float4*>(&Ss[(ty * 4 + i) * FA_SS + tx * 4]) = pr[i];
        if (tx == 0) {
            #pragma unroll
            for (int i = 0; i < 4; i++) alf[ty * 4 + i] = alpha[i];
            if (!hn) {
                #pragma unroll
                for (int i = 0; i < 4; i++) alf[64 + ty * 4 + i] = l[i];
            }
        }
        __syncthreads();   // (a) P/alpha/K-next visible

        // prefetch V[kt+1] (latency hidden under PV)
        float4 vr0, vr1, vr2, vr3;
        if (hn) {
            const float* vn = vp + (size_t)((kt + 1) * 64 + li) * HD + c0;
            vr0 = *reinterpret_cast<const float4*>(vn + 0);
            vr1 = *reinterpret_cast<const float4*>(vn + 4);
            vr2 = *reinterpret_cast<const float4*>(vn + 8);
            vr3 = *reinterpret_cast<const float4*>(vn + 12);
        }

        // ---- PV: rescale O, accumulate P @ V ----
        const u64 al2 = dup2(alf[li]);
        #pragma unroll
        for (int i = 0; i < 8; i++) o2[i] = fmul2(o2[i], al2);

        #pragma unroll 2
        for (int j0 = 0; j0 < 64; j0 += 4) {
            float4 pq = *reinterpret_cast<const float4*>(&Ss[li * FA_SS + j0]);
            FA_PV(pq.x, j0 + 0);
            FA_PV(pq.y, j0 + 1);
            FA_PV(pq.z, j0 + 2);
            FA_PV(pq.w, j0 + 3);
        }

        // store prefetched V (natural) -> next buffer
        if (hn) {
            float* Vn = Vs2 + nxt * 4096 + li * 64 + c0;
            *reinterpret_cast<float4*>(Vn + 0)  = vr0;
            *reinterpret_cast<float4*>(Vn + 4)  = vr1;
            *reinterpret_cast<float4*>(Vn + 8)  = vr2;
            *reinterpret_cast<float4*>(Vn + 12) = vr3;
        }
        __syncthreads();   // (b) Ss free to rewrite; V-next visible
    }

    // Normalize and store into [B,T,C] layout
    const u64 il2 = dup2(1.0f / alf[64 + li]);
    const int b = bh >> 4, h = bh & (NH - 1);
    float* outp = g_att + (size_t)(b * T_SZ + qbase + li) * C_SZ + h * HD + c0;
    ulonglong2* op = reinterpret_cast<ulonglong2*>(outp);
    ulonglong2 w0, w1;
    w0.x = fmul2(o2[0], il2); w0.y = fmul2(o2[1], il2);
    w1.x = fmul2(o2[2], il2); w1.y = fmul2(o2[3], il2);
    op[0] = w0;
    op[1] = w1;
    w0.x = fmul2(o2[4], il2); w0.y = fmul2(o2[5], il2);
    w1.x = fmul2(o2[6], il2); w1.y = fmul2(o2[7], il2);
    op[2] = w0;
    op[3] = w1;
}

// ---------------------------------------------------------------------------
extern "C" void kernel_launch(void* const* d_in, const int* in_sizes, int n_in,
                              void* d_out, int out_size)
{
    const float* x     = (const float*)d_in[0];
    const float* Wqkv  = (const float*)d_in[1];
    const float* bqkv  = (const float*)d_in[2];
    const float* Wproj = (const float*)d_in[3];
    const float* bproj = (const float*)d_in[4];
    float* out = (float*)d_out;
    (void)in_sizes; (void)n_in; (void)out_size;

    cudaFuncSetAttribute(flash_attn, cudaFuncAttributeMaxDynamicSharedMemorySize,
                         FA_SMEM_BYTES);

    // 1) QKV projection (proven FFMA2 SGEMM) + scatter to [B,H,T,hd]
    sgemm_qkv<<<dim3(N_QKV / BN, M_ROWS / BM), 256>>>(
        x, Wqkv, bqkv, M_ROWS, N_QKV, C_SZ);

    // 2) Causal flash attention v2 (register softmax) -> g_att [B,T,C]
    flash_attn<<<dim3(T_SZ / 64, B_SZ * NH), 256, FA_SMEM_BYTES>>>();

    // 3) Output projection (proven FFMA2 SGEMM)
    sgemm_proj<<<dim3(C_SZ / BN, M_ROWS / BM), 256>>>(
        Wproj, bproj, out, M_ROWS, C_SZ, C_SZ);
}